// round 9
// baseline (speedup 1.0000x reference)
#include <cuda_runtime.h>
#include <cuda_fp16.h>
#include <cstdint>

#define DD   512
#define NB   4
#define LQ   128
#define LM   256
#define NDP  256   // d-pairs

// Scratch (allocation-free rule: __device__ globals)
__device__ float    g_q[NB * LQ * DD];      // q = input_emb @ Wq^T + b0 (fp32)
__device__ uint32_t g_mph[NB * LM * NDP];   // mp packed half2, m-major: [n][m][dp]

__device__ __forceinline__ void mma_tf32(
    float& c0, float& c1, float& c2, float& c3,
    uint32_t a0, uint32_t a1, uint32_t a2, uint32_t a3,
    uint32_t b0, uint32_t b1)
{
    asm volatile(
        "mma.sync.aligned.m16n8k8.row.col.f32.tf32.tf32.f32 "
        "{%0,%1,%2,%3}, {%4,%5,%6,%7}, {%8,%9}, {%0,%1,%2,%3};"
        : "+f"(c0), "+f"(c1), "+f"(c2), "+f"(c3)
        : "r"(a0), "r"(a1), "r"(a2), "r"(a3), "r"(b0), "r"(b1));
}

__device__ __forceinline__ void cpa16(uint32_t dst, const float* src)
{
    asm volatile("cp.async.cg.shared.global [%0], [%1], 16;\n"
                 :: "r"(dst), "l"(src));
}

__device__ __forceinline__ __half2 tanh2(__half2 x)
{
    uint32_t xi = *(uint32_t*)&x, ri;
    asm("tanh.approx.f16x2 %0, %1;" : "=r"(ri) : "r"(xi));
    return *(__half2*)&ri;
}

// ---------------------------------------------------------------------------
// Tensor-core GEMM (tf32, cp.async double-buffered, XOR-swizzled smem).
// q-part  (blocks 0..127)  : g_q fp32, + bias
// mp-part (blocks 128..383): g_mph packed half2, m-major [n][m][dp]
// ---------------------------------------------------------------------------
__global__ __launch_bounds__(128, 6) void gemm_tc_kernel(
    const float* __restrict__ inp, const float* __restrict__ mem,
    const float* __restrict__ W0, const float* __restrict__ b0)
{
    __shared__ float As[2][32 * 32];
    __shared__ float Bs[2][64 * 32];

    const int bx = blockIdx.x;
    const float* A;
    int off, r0, e0;
    bool isq;
    if (bx < 128) {
        A = inp; off = 0; isq = true;
        r0 = (bx >> 3) * 32; e0 = (bx & 7) * 64;
    } else {
        const int i = bx - 128;
        A = mem; off = DD; isq = false;
        r0 = (i >> 3) * 32; e0 = (i & 7) * 64;
    }

    const int t = threadIdx.x;
    const int wid = t >> 5, lane = t & 31;
    const int lx = lane & 3, ly = lane >> 2;
    const int swz = 4 * ly;

    const uint32_t sAs = (uint32_t)__cvta_generic_to_shared(As);
    const uint32_t sBs = (uint32_t)__cvta_generic_to_shared(Bs);

    float c[2][2][4];
#pragma unroll
    for (int mt = 0; mt < 2; mt++)
#pragma unroll
        for (int nt = 0; nt < 2; nt++)
#pragma unroll
            for (int i = 0; i < 4; i++) c[mt][nt][i] = 0.f;

    const float* aptr = A + (size_t)r0 * DD;
    const float* bptr = W0 + (size_t)e0 * (2 * DD) + off;

    auto load_stage = [&](int s, int k0) {
#pragma unroll
        for (int i = 0; i < 2; i++) {
            const int cid = 2 * t + i;
            const int row = cid >> 3, cc = (cid & 7) * 4;
            const int pc = cc ^ ((row & 7) * 4);
            cpa16(sAs + (uint32_t)((s * 1024 + row * 32 + pc) * 4),
                  aptr + (size_t)row * DD + k0 + cc);
        }
#pragma unroll
        for (int i = 0; i < 4; i++) {
            const int cid = t + i * 128;
            const int row = cid >> 3, cc = (cid & 7) * 4;
            const int pc = cc ^ ((row & 7) * 4);
            cpa16(sBs + (uint32_t)((s * 2048 + row * 32 + pc) * 4),
                  bptr + (size_t)row * (2 * DD) + k0 + cc);
        }
        asm volatile("cp.async.commit_group;\n" ::: "memory");
    };

    load_stage(0, 0);

    const uint32_t* AsU = (const uint32_t*)As;
    const uint32_t* BsU = (const uint32_t*)Bs;

    for (int it = 0; it < 16; it++) {
        if (it + 1 < 16) load_stage((it + 1) & 1, (it + 1) * 32);
        else asm volatile("cp.async.commit_group;\n" ::: "memory");
        asm volatile("cp.async.wait_group 1;\n" ::: "memory");
        __syncthreads();

        const int s = it & 1;
        const uint32_t* Ab = AsU + s * 1024;
        const uint32_t* Bb = BsU + s * 2048;
#pragma unroll
        for (int k8 = 0; k8 < 4; k8++) {
            const int c0 = (k8 * 8 + lx) ^ swz;
            const int c1 = c0 ^ 4;
            uint32_t a[2][4], b[2][2];
#pragma unroll
            for (int mt = 0; mt < 2; mt++) {
                const int rA = mt * 16 + ly;
                a[mt][0] = Ab[rA * 32 + c0];
                a[mt][1] = Ab[(rA + 8) * 32 + c0];
                a[mt][2] = Ab[rA * 32 + c1];
                a[mt][3] = Ab[(rA + 8) * 32 + c1];
            }
#pragma unroll
            for (int nt = 0; nt < 2; nt++) {
                const int rB = wid * 16 + nt * 8 + ly;
                b[nt][0] = Bb[rB * 32 + c0];
                b[nt][1] = Bb[rB * 32 + c1];
            }
#pragma unroll
            for (int mt = 0; mt < 2; mt++)
#pragma unroll
                for (int nt = 0; nt < 2; nt++)
                    mma_tf32(c[mt][nt][0], c[mt][nt][1], c[mt][nt][2], c[mt][nt][3],
                             a[mt][0], a[mt][1], a[mt][2], a[mt][3],
                             b[nt][0], b[nt][1]);
        }
        __syncthreads();
    }

    // epilogue
#pragma unroll
    for (int mt = 0; mt < 2; mt++) {
#pragma unroll
        for (int nt = 0; nt < 2; nt++) {
            const int col = e0 + wid * 16 + nt * 8 + 2 * lx;
            const int rA = r0 + mt * 16 + ly;
            if (isq) {
                float bx0 = b0[col], bx1 = b0[col + 1];
                float2 v0 = make_float2(c[mt][nt][0] + bx0, c[mt][nt][1] + bx1);
                float2 v1 = make_float2(c[mt][nt][2] + bx0, c[mt][nt][3] + bx1);
                *(float2*)&g_q[(size_t)rA * DD + col]       = v0;
                *(float2*)&g_q[(size_t)(rA + 8) * DD + col] = v1;
            } else {
                // m-major packed store: g_mph[n][m][dp]
                const int n_ = rA >> 8;
                const int m_ = rA & 255;
                const int dp = col >> 1;
                __half2 u0 = __floats2half2_rn(c[mt][nt][0], c[mt][nt][1]);
                __half2 u1 = __floats2half2_rn(c[mt][nt][2], c[mt][nt][3]);
                uint32_t* base = g_mph + (size_t)n_ * (LM * NDP);
                base[(size_t)m_ * NDP + dp]       = *(uint32_t*)&u0;
                base[(size_t)(m_ + 8) * NDP + dp] = *(uint32_t*)&u1;
            }
        }
    }
}

// ---------------------------------------------------------------------------
// Fused score+softmax+output. grid = 512 blocks = (n:4, l:128); 256 threads,
// thread t owns m=t. Score: thread streams its own contiguous 1KB mp row via
// 64 LDG.128, register double-buffered (loads issued one g-batch ahead);
// q/w1 broadcast from smem. HADD2+tanh.f16x2+HFMA2, fp16 chains of 4 flushed
// to fp32. Block softmax, then output GEMV with unroll-8 batched loads.
// ---------------------------------------------------------------------------
__global__ __launch_bounds__(256) void attn_fused(
    const float* __restrict__ mem, const unsigned int* __restrict__ mask,
    const float* __restrict__ w1, const float* __restrict__ b1,
    float* __restrict__ out)
{
    __shared__ uint2 sQW[NDP];   // {q half2, w1 half2} per dp
    __shared__ float satt[LM];
    __shared__ float red[8];

    const int b = blockIdx.x;
    const int n = b >> 7, l = b & 127;
    const int t = threadIdx.x;       // == m
    const int wid = t >> 5, lane = t & 31;

    // preload q-row(l) + w1, packed half2 (thread t -> dp t)
    {
        const float2 qv = *(const float2*)&g_q[(size_t)(n * LQ + l) * DD + 2 * t];
        const float2 wv = *(const float2*)&w1[2 * t];
        __half2 qh = __floats2half2_rn(qv.x, qv.y);
        __half2 wh = __floats2half2_rn(wv.x, wv.y);
        uint2 u;
        u.x = *(uint32_t*)&qh;
        u.y = *(uint32_t*)&wh;
        sQW[t] = u;
    }
    __syncthreads();

    // ---- score: s = b1 + sum_dp w1.tanh(q+mp), pipelined wide loads ----
    const uint4* mrow = (const uint4*)(g_mph + (size_t)n * (LM * NDP) + (size_t)t * NDP);
    float accf = 0.f;
    uint4 c0 = mrow[0], c1 = mrow[1];
#pragma unroll 4
    for (int g = 0; g < 32; g++) {
        uint4 n0, n1;
        if (g < 31) { n0 = mrow[2 * g + 2]; n1 = mrow[2 * g + 3]; }
        __half2 a0 = __float2half2_rn(0.f);
        __half2 a1 = __float2half2_rn(0.f);
        const uint32_t cw[8] = {c0.x, c0.y, c0.z, c0.w, c1.x, c1.y, c1.z, c1.w};
#pragma unroll
        for (int j = 0; j < 8; j++) {
            uint2 qw = sQW[g * 8 + j];
            __half2 x = __hadd2(*(__half2*)&qw.x, *(const __half2*)&cw[j]);
            __half2 th = tanh2(x);
            if (j < 4) a0 = __hfma2(*(__half2*)&qw.y, th, a0);
            else       a1 = __hfma2(*(__half2*)&qw.y, th, a1);
        }
        float2 f0 = __half22float2(a0);
        float2 f1 = __half22float2(a1);
        accf += (f0.x + f0.y) + (f1.x + f1.y);
        c0 = n0; c1 = n1;
    }
    float s = accf + b1[0];
    if (mask[(size_t)(n * LQ + l) * LM + t] == 0u)   // bool promoted to 4B
        s = -3.402823466e38f;

    // ---- block softmax over 256 threads ----
    float mx = s;
#pragma unroll
    for (int o = 16; o > 0; o >>= 1)
        mx = fmaxf(mx, __shfl_xor_sync(0xffffffffu, mx, o));
    if (lane == 0) red[wid] = mx;
    __syncthreads();
#pragma unroll
    for (int k = 0; k < 8; k++) mx = fmaxf(mx, red[k]);

    float e = __expf(s - mx);
    float sum = e;
#pragma unroll
    for (int o = 16; o > 0; o >>= 1)
        sum += __shfl_xor_sync(0xffffffffu, sum, o);
    __syncthreads();                 // all reads of red (max) done
    if (lane == 0) red[wid] = sum;
    satt[t] = e;
    __syncthreads();
    sum = 0.f;
#pragma unroll
    for (int k = 0; k < 8; k++) sum += red[k];
    const float inv = 1.f / sum;

    // ---- output GEMV: thread t owns dims (2t, 2t+1), batched loads (MLP 8) ----
    const float* memn = mem + (size_t)n * LM * DD + 2 * t;
    float ox = 0.f, oy = 0.f;
    for (int mb = 0; mb < LM; mb += 8) {
        float2 v[8];
#pragma unroll
        for (int j = 0; j < 8; j++)
            v[j] = *(const float2*)&memn[(size_t)(mb + j) * DD];
#pragma unroll
        for (int j = 0; j < 8; j++) {
            const float a = satt[mb + j];
            ox = fmaf(a, v[j].x, ox);
            oy = fmaf(a, v[j].y, oy);
        }
    }
    float2 o2 = make_float2(ox * inv, oy * inv);
    *(float2*)&out[(size_t)(n * LQ + l) * DD + 2 * t] = o2;
}

extern "C" void kernel_launch(void* const* d_in, const int* in_sizes, int n_in,
                              void* d_out, int out_size)
{
    const float*        inp  = (const float*)d_in[0];        // (4,128,512)
    const float*        mem  = (const float*)d_in[1];        // (4,256,512)
    const unsigned int* mask = (const unsigned int*)d_in[2]; // (4,128,256) bool->4B
    const float*        W0   = (const float*)d_in[3];        // (512,1024)
    const float*        b0   = (const float*)d_in[4];        // (512)
    const float*        w1   = (const float*)d_in[5];        // (1,512)
    const float*        b1   = (const float*)d_in[6];        // (1)
    float* out = (float*)d_out;                              // (4,128,512)

    gemm_tc_kernel<<<384, 128>>>(inp, mem, W0, b0);
    attn_fused<<<512, 256>>>(mem, mask, w1, b1, out);
}

// round 10
// speedup vs baseline: 1.2819x; 1.2819x over previous
#include <cuda_runtime.h>
#include <cuda_fp16.h>
#include <cstdint>

#define DD   512
#define NB   4
#define LQ   128
#define LM   256
#define NDP  256   // d-pairs

// Scratch (allocation-free rule: __device__ globals)
__device__ float    g_q[NB * LQ * DD];      // q = input_emb @ Wq^T + b0 (fp32)
__device__ uint32_t g_mph[NB * LM * NDP];   // mp packed half2, m-major: [n][m][dp]
__device__ float    g_sc[NB * LQ * LM];     // raw scores (pre-mask/softmax)

__device__ __forceinline__ void mma_tf32(
    float& c0, float& c1, float& c2, float& c3,
    uint32_t a0, uint32_t a1, uint32_t a2, uint32_t a3,
    uint32_t b0, uint32_t b1)
{
    asm volatile(
        "mma.sync.aligned.m16n8k8.row.col.f32.tf32.tf32.f32 "
        "{%0,%1,%2,%3}, {%4,%5,%6,%7}, {%8,%9}, {%0,%1,%2,%3};"
        : "+f"(c0), "+f"(c1), "+f"(c2), "+f"(c3)
        : "r"(a0), "r"(a1), "r"(a2), "r"(a3), "r"(b0), "r"(b1));
}

__device__ __forceinline__ void cpa16(uint32_t dst, const void* src)
{
    asm volatile("cp.async.cg.shared.global [%0], [%1], 16;\n"
                 :: "r"(dst), "l"(src));
}

__device__ __forceinline__ __half2 tanh2(__half2 x)
{
    uint32_t xi = *(uint32_t*)&x, ri;
    asm("tanh.approx.f16x2 %0, %1;" : "=r"(ri) : "r"(xi));
    return *(__half2*)&ri;
}

__device__ __forceinline__ __half2 H2(uint32_t u) { return *(__half2*)&u; }

// ---------------------------------------------------------------------------
// Tensor-core GEMM (tf32, cp.async double-buffered, XOR-swizzled smem).
// q-part  (blocks 0..127)  : g_q fp32, + bias
// mp-part (blocks 128..383): g_mph packed half2, m-major [n][m][dp]
// ---------------------------------------------------------------------------
__global__ __launch_bounds__(128, 6) void gemm_tc_kernel(
    const float* __restrict__ inp, const float* __restrict__ mem,
    const float* __restrict__ W0, const float* __restrict__ b0)
{
    __shared__ float As[2][32 * 32];
    __shared__ float Bs[2][64 * 32];

    const int bx = blockIdx.x;
    const float* A;
    int off, r0, e0;
    bool isq;
    if (bx < 128) {
        A = inp; off = 0; isq = true;
        r0 = (bx >> 3) * 32; e0 = (bx & 7) * 64;
    } else {
        const int i = bx - 128;
        A = mem; off = DD; isq = false;
        r0 = (i >> 3) * 32; e0 = (i & 7) * 64;
    }

    const int t = threadIdx.x;
    const int wid = t >> 5, lane = t & 31;
    const int lx = lane & 3, ly = lane >> 2;
    const int swz = 4 * ly;

    const uint32_t sAs = (uint32_t)__cvta_generic_to_shared(As);
    const uint32_t sBs = (uint32_t)__cvta_generic_to_shared(Bs);

    float c[2][2][4];
#pragma unroll
    for (int mt = 0; mt < 2; mt++)
#pragma unroll
        for (int nt = 0; nt < 2; nt++)
#pragma unroll
            for (int i = 0; i < 4; i++) c[mt][nt][i] = 0.f;

    const float* aptr = A + (size_t)r0 * DD;
    const float* bptr = W0 + (size_t)e0 * (2 * DD) + off;

    auto load_stage = [&](int s, int k0) {
#pragma unroll
        for (int i = 0; i < 2; i++) {
            const int cid = 2 * t + i;
            const int row = cid >> 3, cc = (cid & 7) * 4;
            const int pc = cc ^ ((row & 7) * 4);
            cpa16(sAs + (uint32_t)((s * 1024 + row * 32 + pc) * 4),
                  aptr + (size_t)row * DD + k0 + cc);
        }
#pragma unroll
        for (int i = 0; i < 4; i++) {
            const int cid = t + i * 128;
            const int row = cid >> 3, cc = (cid & 7) * 4;
            const int pc = cc ^ ((row & 7) * 4);
            cpa16(sBs + (uint32_t)((s * 2048 + row * 32 + pc) * 4),
                  bptr + (size_t)row * (2 * DD) + k0 + cc);
        }
        asm volatile("cp.async.commit_group;\n" ::: "memory");
    };

    load_stage(0, 0);

    const uint32_t* AsU = (const uint32_t*)As;
    const uint32_t* BsU = (const uint32_t*)Bs;

    for (int it = 0; it < 16; it++) {
        if (it + 1 < 16) load_stage((it + 1) & 1, (it + 1) * 32);
        else asm volatile("cp.async.commit_group;\n" ::: "memory");
        asm volatile("cp.async.wait_group 1;\n" ::: "memory");
        __syncthreads();

        const int s = it & 1;
        const uint32_t* Ab = AsU + s * 1024;
        const uint32_t* Bb = BsU + s * 2048;
#pragma unroll
        for (int k8 = 0; k8 < 4; k8++) {
            const int c0 = (k8 * 8 + lx) ^ swz;
            const int c1 = c0 ^ 4;
            uint32_t a[2][4], b[2][2];
#pragma unroll
            for (int mt = 0; mt < 2; mt++) {
                const int rA = mt * 16 + ly;
                a[mt][0] = Ab[rA * 32 + c0];
                a[mt][1] = Ab[(rA + 8) * 32 + c0];
                a[mt][2] = Ab[rA * 32 + c1];
                a[mt][3] = Ab[(rA + 8) * 32 + c1];
            }
#pragma unroll
            for (int nt = 0; nt < 2; nt++) {
                const int rB = wid * 16 + nt * 8 + ly;
                b[nt][0] = Bb[rB * 32 + c0];
                b[nt][1] = Bb[rB * 32 + c1];
            }
#pragma unroll
            for (int mt = 0; mt < 2; mt++)
#pragma unroll
                for (int nt = 0; nt < 2; nt++)
                    mma_tf32(c[mt][nt][0], c[mt][nt][1], c[mt][nt][2], c[mt][nt][3],
                             a[mt][0], a[mt][1], a[mt][2], a[mt][3],
                             b[nt][0], b[nt][1]);
        }
        __syncthreads();
    }

    // epilogue
#pragma unroll
    for (int mt = 0; mt < 2; mt++) {
#pragma unroll
        for (int nt = 0; nt < 2; nt++) {
            const int col = e0 + wid * 16 + nt * 8 + 2 * lx;
            const int rA = r0 + mt * 16 + ly;
            if (isq) {
                float bx0 = b0[col], bx1 = b0[col + 1];
                float2 v0 = make_float2(c[mt][nt][0] + bx0, c[mt][nt][1] + bx1);
                float2 v1 = make_float2(c[mt][nt][2] + bx0, c[mt][nt][3] + bx1);
                *(float2*)&g_q[(size_t)rA * DD + col]       = v0;
                *(float2*)&g_q[(size_t)(rA + 8) * DD + col] = v1;
            } else {
                // m-major packed store: g_mph[n][m][dp]
                const int n_ = rA >> 8;
                const int m_ = rA & 255;
                const int dp = col >> 1;
                __half2 u0 = __floats2half2_rn(c[mt][nt][0], c[mt][nt][1]);
                __half2 u1 = __floats2half2_rn(c[mt][nt][2], c[mt][nt][3]);
                uint32_t* base = g_mph + (size_t)n_ * (LM * NDP);
                base[(size_t)m_ * NDP + dp]       = *(uint32_t*)&u0;
                base[(size_t)(m_ + 8) * NDP + dp] = *(uint32_t*)&u1;
            }
        }
    }
}

// ---------------------------------------------------------------------------
// Score kernel (cp.async-staged, zero-reduction):
//   g_sc[n,l,m] = b1 + sum_d w1[d]*tanh(q[n,l,d]+mp[n,m,d])
// grid = 256 blocks: n(4) x l-tile(16, 8 l) x m-split(4, 64 m).
// 256 threads = 8 l-warps; lane = m_local(16) x dp_half(2).
// mp streamed as 4 tiles of [16 m][256 dp] half2 via double-buffered
// cp.async (16KB/stage); SMEM reads are LDS.128, XOR-by-m swizzled.
// q+w1 pre-packed interleaved in smem, read as broadcast.
// Per-thread 128-d reduction in registers (fp16 chains of 8 -> fp32),
// one shfl_xor(16) merges dp-halves. Static smem = 48KB exactly.
// ---------------------------------------------------------------------------
__global__ __launch_bounds__(256, 2) void score_kernel(
    const float* __restrict__ w1v, const float* __restrict__ b1)
{
    __shared__ uint4 sqw[8][128];       // [l][c]: {q(2c),w(2c),q(2c+1),w(2c+1)} 16KB
    __shared__ uint4 smp[2][16][64];    // [stage][m][chunk phys] 32KB

    const int b = blockIdx.x;
    const int n = b >> 6;
    const int rem = b & 63;
    const int l0 = (rem >> 2) * 8;
    const int m0 = (rem & 2 ? (rem & 1 ? 192 : 128) : (rem & 1 ? 64 : 0));
    const int t = threadIdx.x;
    const int wid = t >> 5, lane = t & 31;
    const int m_l = lane & 15, dh = lane >> 4;

    const uint32_t smp_base = (uint32_t)__cvta_generic_to_shared(smp);

    // ---- fill q+w1 interleaved half2 table ----
#pragma unroll
    for (int i = 0; i < 4; i++) {
        const int idx = t + i * 256;         // 0..1023
        const int l = idx >> 7, c = idx & 127;
        float4 qv = *(const float4*)&g_q[(size_t)(n * LQ + l0 + l) * DD + 4 * c];
        float4 wv = *(const float4*)&w1v[4 * c];
        __half2 q0 = __floats2half2_rn(qv.x, qv.y);
        __half2 q1 = __floats2half2_rn(qv.z, qv.w);
        __half2 w0 = __floats2half2_rn(wv.x, wv.y);
        __half2 w1h = __floats2half2_rn(wv.z, wv.w);
        sqw[l][c] = make_uint4(*(uint32_t*)&q0, *(uint32_t*)&w0,
                               *(uint32_t*)&q1, *(uint32_t*)&w1h);
    }

    // ---- mp tile loader: [16 m][64 uint4 chunks], phys chunk = dp4 ^ m ----
    auto load_tile = [&](int s, int mt0) {
        const uint4* src = (const uint4*)(g_mph + ((size_t)n * LM + mt0) * NDP);
#pragma unroll
        for (int i = 0; i < 4; i++) {
            const int c = t + i * 256;          // 0..1023
            const int m = c >> 6, dp4 = c & 63;
            cpa16(smp_base + (uint32_t)(((s * 1024) + m * 64 + (dp4 ^ m)) * 16),
                  src + c);
        }
        asm volatile("cp.async.commit_group;\n" ::: "memory");
    };

    load_tile(0, m0);

    const float b1v = b1[0];
    const int dp4base = dh * 32;

    for (int tile = 0; tile < 4; tile++) {
        if (tile + 1 < 4) load_tile((tile + 1) & 1, m0 + (tile + 1) * 16);
        else asm volatile("cp.async.commit_group;\n" ::: "memory");
        asm volatile("cp.async.wait_group 1;\n" ::: "memory");
        __syncthreads();

        const int s = tile & 1;
        float part = 0.f;
#pragma unroll
        for (int j0 = 0; j0 < 32; j0 += 8) {
            __half2 a0 = __float2half2_rn(0.f);
            __half2 a1 = __float2half2_rn(0.f);
            __half2 a2 = __float2half2_rn(0.f);
            __half2 a3 = __float2half2_rn(0.f);
#pragma unroll
            for (int jj = 0; jj < 8; jj++) {
                const int dp4 = dp4base + j0 + jj;
                const uint4 mp = smp[s][m_l][dp4 ^ m_l];
                const uint4 s0 = sqw[wid][dp4 * 2];
                const uint4 s1 = sqw[wid][dp4 * 2 + 1];
                a0 = __hfma2(H2(s0.y), tanh2(__hadd2(H2(s0.x), H2(mp.x))), a0);
                a1 = __hfma2(H2(s0.w), tanh2(__hadd2(H2(s0.z), H2(mp.y))), a1);
                a2 = __hfma2(H2(s1.y), tanh2(__hadd2(H2(s1.x), H2(mp.z))), a2);
                a3 = __hfma2(H2(s1.w), tanh2(__hadd2(H2(s1.z), H2(mp.w))), a3);
            }
            float2 f0 = __half22float2(__hadd2(a0, a1));
            float2 f1 = __half22float2(__hadd2(a2, a3));
            part += (f0.x + f0.y) + (f1.x + f1.y);
        }
        // merge the two dp-halves
        part += __shfl_xor_sync(0xffffffffu, part, 16);
        if (dh == 0)
            g_sc[(size_t)(n * LQ + l0 + wid) * LM + m0 + tile * 16 + m_l] = part + b1v;
        __syncthreads();
    }
}

// ---------------------------------------------------------------------------
// Softmax + output: out[n,l,:] = softmax(mask(sc[n,l,:])) @ memory[n]
// grid = 512 blocks: n(4) x l-tile(32, 4 rows) x d-split(4, 128 d's).
// (R5's proven kernel.)
// ---------------------------------------------------------------------------
__global__ __launch_bounds__(128) void out_kernel(
    const float* __restrict__ mem, const unsigned int* __restrict__ mask,
    float* __restrict__ out)
{
    __shared__ float att[4][LM];

    const int b = blockIdx.x;
    const int n = b >> 7;
    const int rem = b & 127;
    const int l0 = (rem >> 2) * 4;
    const int d0 = (rem & 3) * 128;
    const int t = threadIdx.x;
    const int w = t >> 5, lane = t & 31;

    {
        const int l = w;
        const float* srow = g_sc + (size_t)(n * LQ + l0 + l) * LM;
        const unsigned int* mrow = mask + (size_t)(n * LQ + l0 + l) * LM;
        const float NEG = -3.402823466e38f;
        float s[8];
        float mx = NEG;
#pragma unroll
        for (int k = 0; k < 8; k++) {
            int m = lane + 32 * k;
            float v = srow[m];
            if (mrow[m] == 0u) v = NEG;   // bool promoted: nonzero bits == true
            s[k] = v;
            mx = fmaxf(mx, v);
        }
#pragma unroll
        for (int o = 16; o > 0; o >>= 1)
            mx = fmaxf(mx, __shfl_xor_sync(0xffffffffu, mx, o));
        float sum = 0.f;
#pragma unroll
        for (int k = 0; k < 8; k++) {
            s[k] = __expf(s[k] - mx);
            sum += s[k];
        }
#pragma unroll
        for (int o = 16; o > 0; o >>= 1)
            sum += __shfl_xor_sync(0xffffffffu, sum, o);
        const float inv = 1.f / sum;
#pragma unroll
        for (int k = 0; k < 8; k++)
            att[l][lane + 32 * k] = s[k] * inv;
    }
    __syncthreads();

    {
        const int l = w;
        const int dbase = d0 + lane * 4;
        const float* memn = mem + (size_t)n * LM * DD + dbase;
        float4 o0 = make_float4(0.f, 0.f, 0.f, 0.f);
#pragma unroll 8
        for (int m = 0; m < LM; m++) {
            const float a = att[l][m];
            const float4 v = *(const float4*)&memn[(size_t)m * DD];
            o0.x = fmaf(a, v.x, o0.x); o0.y = fmaf(a, v.y, o0.y);
            o0.z = fmaf(a, v.z, o0.z); o0.w = fmaf(a, v.w, o0.w);
        }
        *(float4*)&out[(size_t)(n * LQ + l0 + l) * DD + dbase] = o0;
    }
}

extern "C" void kernel_launch(void* const* d_in, const int* in_sizes, int n_in,
                              void* d_out, int out_size)
{
    const float*        inp  = (const float*)d_in[0];        // (4,128,512)
    const float*        mem  = (const float*)d_in[1];        // (4,256,512)
    const unsigned int* mask = (const unsigned int*)d_in[2]; // (4,128,256) bool->4B
    const float*        W0   = (const float*)d_in[3];        // (512,1024)
    const float*        b0   = (const float*)d_in[4];        // (512)
    const float*        w1   = (const float*)d_in[5];        // (1,512)
    const float*        b1   = (const float*)d_in[6];        // (1)
    float* out = (float*)d_out;                              // (4,128,512)

    gemm_tc_kernel<<<384, 128>>>(inp, mem, W0, b0);
    score_kernel<<<256, 256>>>(w1, b1);
    out_kernel<<<512, 128>>>(mem, mask, out);
}